// round 4
// baseline (speedup 1.0000x reference)
#include <cuda_runtime.h>

// PermutationInvariantNet: B=8, N=256, IN_DIM=2, D=128, H=512, L=2
// Tokens T = B*N = 2048. All fp32.

#define T_TOK 2048
#define NB 8
#define NN 256
#define DD 128
#define HH 512
#define LN_EPS 1e-5f

// -------- scratch (device globals; no allocation allowed) --------
__device__ float g_h[T_TOK * DD];        // hidden state      (1 MB)
__device__ float g_cat[T_TOK * 2 * DD];  // [h, pooled]       (2 MB)
__device__ float g_ff[T_TOK * HH];       // ff intermediate   (4 MB)
__device__ float g_tmp[T_TOK * DD];      // gemm output       (1 MB)

// -------- LayerNorm stats over 128 threads (one token per block) --------
__device__ __forceinline__ void ln_stats_128(float y, float& mean, float& rstd) {
    __shared__ float sh[8];
    float s = y, q = y * y;
#pragma unroll
    for (int o = 16; o > 0; o >>= 1) {
        s += __shfl_xor_sync(0xffffffffu, s, o);
        q += __shfl_xor_sync(0xffffffffu, q, o);
    }
    int lane = threadIdx.x & 31, w = threadIdx.x >> 5;
    if (lane == 0) { sh[w] = s; sh[4 + w] = q; }
    __syncthreads();
    s = sh[0] + sh[1] + sh[2] + sh[3];
    q = sh[4] + sh[5] + sh[6] + sh[7];
    mean = s * (1.0f / DD);
    float var = q * (1.0f / DD) - mean * mean;
    rstd = rsqrtf(var + LN_EPS);
}

// -------- embed + LN:  h = LN(x @ We + be) --------
__global__ void __launch_bounds__(128)
embed_ln_kernel(const float* __restrict__ x, const float* __restrict__ We,
                const float* __restrict__ be, const float* __restrict__ ge,
                const float* __restrict__ bge) {
    int t = blockIdx.x, d = threadIdx.x;
    float x0 = x[t * 2 + 0];
    float x1 = x[t * 2 + 1];
    float y = fmaf(x0, We[d], fmaf(x1, We[DD + d], be[d]));
    float mean, rstd;
    ln_stats_128(y, mean, rstd);
    g_h[t * DD + d] = (y - mean) * rstd * ge[d] + bge[d];
}

// -------- LOO max pool + concat:  g_cat = [h, loo_max(h)] --------
// grid (8 batches, 4 n-quarters), 128 threads (one per feature d).
// Stats computed redundantly per quarter-block (cheap), writes split by quarter.
__global__ void __launch_bounds__(128)
pool_prepare_kernel() {
    int b = blockIdx.x;
    int q = blockIdx.y;
    int d = threadIdx.x;
    const float* hb = g_h + b * NN * DD;

    float m1 = -3.402823466e38f, m2 = -3.402823466e38f;
    int i1 = 0;
#pragma unroll 8
    for (int n = 0; n < NN; n++) {
        float v = hb[n * DD + d];
        if (v > m1) { m2 = m1; m1 = v; i1 = n; }
        else if (v > m2) { m2 = v; }
    }
    // Leave-one-out max: max2 at the argmax position, max1 elsewhere.
    // Tie-correct: duplicated max -> m2 == m1, so every position gets m1.
    float* cb = g_cat + b * NN * 2 * DD;
    int n0 = q * (NN / 4);
#pragma unroll 4
    for (int n = n0; n < n0 + NN / 4; n++) {
        float hv = hb[n * DD + d];
        cb[n * 2 * DD + d] = hv;
        cb[n * 2 * DD + DD + d] = (n == i1) ? m2 : m1;
    }
}

// -------- generic small GEMM: C[T,NOUT] = A[T,KDIM] @ W[KDIM,NOUT] + bias --------
// SRC: 0=g_h, 1=g_cat, 2=g_ff ; DST: 0=g_tmp, 1=g_ff
// Block = (NX, NY) threads, covers TM tokens x NOUT cols. 2048/TM blocks.
// A tile is register-cached per KT tile (broadcast LDS), inner loop = RC W-loads
// + RR*RC FFMAs per k-step -> FFMA-issue-bound.
template <int KDIM, int NOUT, int TM, int KT, int NX, int NY, bool RELU, int SRC, int DST>
__global__ void __launch_bounds__(NX* NY)
gemm_kernel(const float* __restrict__ W, const float* __restrict__ bias) {
    constexpr int RR = TM / NY;     // rows per thread
    constexpr int RC = NOUT / NX;   // cols per thread
    constexpr int NT = NX * NY;

    __shared__ float As[TM][KT];
    __shared__ float Ws[KT][NOUT];

    const float* A = (SRC == 0) ? g_h : (SRC == 1) ? g_cat : g_ff;
    float* C = (DST == 0) ? g_tmp : g_ff;

    const int tx = threadIdx.x, ty = threadIdx.y;
    const int tid = ty * NX + tx;
    const int row0 = blockIdx.x * TM;

    float acc[RR][RC];
#pragma unroll
    for (int r = 0; r < RR; r++)
#pragma unroll
        for (int c = 0; c < RC; c++) acc[r][c] = 0.0f;

    for (int k0 = 0; k0 < KDIM; k0 += KT) {
        __syncthreads();  // previous tile fully consumed
        // load A tile (TM x KT) — coalesced in KT-chunks
#pragma unroll
        for (int i = tid; i < TM * KT; i += NT) {
            int r = i / KT, cc = i % KT;
            As[r][cc] = A[(row0 + r) * KDIM + k0 + cc];
        }
        // load W tile (KT x NOUT) — fully coalesced
#pragma unroll
        for (int i = tid; i < KT * NOUT; i += NT) {
            int r = i / NOUT, cc = i % NOUT;
            Ws[r][cc] = W[(k0 + r) * NOUT + cc];
        }
        __syncthreads();

        // register-cache this thread's A rows for the whole KT tile
        float areg[RR][KT];
#pragma unroll
        for (int r = 0; r < RR; r++) {
#pragma unroll
            for (int kk = 0; kk < KT; kk += 4) {
                float4 v = *reinterpret_cast<const float4*>(&As[ty + r * NY][kk]);
                areg[r][kk + 0] = v.x; areg[r][kk + 1] = v.y;
                areg[r][kk + 2] = v.z; areg[r][kk + 3] = v.w;
            }
        }
#pragma unroll
        for (int kk = 0; kk < KT; kk++) {
            float w[RC];
#pragma unroll
            for (int c = 0; c < RC; c++) w[c] = Ws[kk][tx + c * NX];
#pragma unroll
            for (int r = 0; r < RR; r++)
#pragma unroll
                for (int c = 0; c < RC; c++)
                    acc[r][c] = fmaf(areg[r][kk], w[c], acc[r][c]);
        }
    }

#pragma unroll
    for (int r = 0; r < RR; r++) {
        int row = row0 + ty + r * NY;
#pragma unroll
        for (int c = 0; c < RC; c++) {
            int col = tx + c * NX;
            float v = acc[r][c] + bias[col];
            if (RELU) v = fmaxf(v, 0.0f);
            C[row * NOUT + col] = v;
        }
    }
}

// -------- residual + LN:  out = LN(g_h + g_tmp) * g + b --------
// FINAL=false: write back into g_h (in-place safe: per-thread read-then-write,
// LN reduction uses registers only). FINAL=true: write to d_out.
template <bool FINAL>
__global__ void __launch_bounds__(128)
res_ln_kernel(const float* __restrict__ g, const float* __restrict__ b,
              float* __restrict__ out) {
    int t = blockIdx.x, d = threadIdx.x;
    int idx = t * DD + d;
    float y = g_h[idx] + g_tmp[idx];
    float mean, rstd;
    ln_stats_128(y, mean, rstd);
    float r = (y - mean) * rstd * g[d] + b[d];
    if (FINAL) out[idx] = r;
    else       g_h[idx] = r;
}

extern "C" void kernel_launch(void* const* d_in, const int* in_sizes, int n_in,
                              void* d_out, int out_size) {
    const float* x   = (const float*)d_in[0];   // (8,256,2)
    const float* We  = (const float*)d_in[1];   // (2,128)
    const float* be  = (const float*)d_in[2];   // (128,)
    const float* ge  = (const float*)d_in[3];
    const float* bge = (const float*)d_in[4];
    const float* Wp  = (const float*)d_in[5];   // (2,256,128)
    const float* bp  = (const float*)d_in[6];   // (2,128)
    const float* gp  = (const float*)d_in[7];
    const float* bgp = (const float*)d_in[8];
    const float* W1  = (const float*)d_in[9];   // (2,128,512)
    const float* b1  = (const float*)d_in[10];  // (2,512)
    const float* W2  = (const float*)d_in[11];  // (2,512,128)
    const float* b2  = (const float*)d_in[12];  // (2,128)
    const float* gf  = (const float*)d_in[13];
    const float* bgf = (const float*)d_in[14];
    float* out = (float*)d_out;                 // (8,256,128) fp32

    embed_ln_kernel<<<T_TOK, 128>>>(x, We, be, ge, bge);

    for (int i = 0; i < 2; i++) {
        pool_prepare_kernel<<<dim3(NB, 4), 128>>>();

        // pool linear: g_cat(2048x256) @ Wp[i](256x128) -> g_tmp
        gemm_kernel<256, 128, 16, 32, 32, 8, false, 1, 0>
            <<<T_TOK / 16, dim3(32, 8)>>>(Wp + i * 2 * DD * DD, bp + i * DD);
        res_ln_kernel<false><<<T_TOK, 128>>>(gp + i * DD, bgp + i * DD, nullptr);

        // ff1: g_h(2048x128) @ W1[i](128x512) + relu -> g_ff
        gemm_kernel<128, 512, 16, 16, 64, 4, true, 0, 1>
            <<<T_TOK / 16, dim3(64, 4)>>>(W1 + i * DD * HH, b1 + i * HH);

        // ff2: g_ff(2048x512) @ W2[i](512x128) -> g_tmp
        gemm_kernel<512, 128, 16, 32, 32, 8, false, 2, 0>
            <<<T_TOK / 16, dim3(32, 8)>>>(W2 + i * HH * DD, b2 + i * DD);

        if (i == 1)
            res_ln_kernel<true><<<T_TOK, 128>>>(gf + i * DD, bgf + i * DD, out);
        else
            res_ln_kernel<false><<<T_TOK, 128>>>(gf + i * DD, bgf + i * DD, nullptr);
    }
}

// round 5
// speedup vs baseline: 1.3088x; 1.3088x over previous
#include <cuda_runtime.h>

// PermutationInvariantNet: B=8, N=256, IN_DIM=2, D=128, H=512, L=2
// Tokens T = B*N = 2048. All fp32.
// 7-launch graph: embed, 2x { stats, pool_gemm+LN, ff1+relu+ff2+res+LN }.

#define T_TOK 2048
#define NB 8
#define NN 256
#define DD 128
#define HH 512
#define LN_EPS 1e-5f
#define NEG_INF -3.402823466e38f

// -------- scratch (device globals; no allocation allowed) --------
__device__ float g_h[T_TOK * DD];     // hidden state (1 MB)
__device__ float g_m1[NB * DD];       // per-batch per-feature max
__device__ float g_m2[NB * DD];       // second max
__device__ int   g_i1[NB * DD];       // argmax (n index within batch)

// -------- warp-local LayerNorm stats: all 128 row values live in one warp --------
__device__ __forceinline__ void warp_ln_stats(float s, float q, float& mean, float& rstd) {
#pragma unroll
    for (int o = 16; o > 0; o >>= 1) {
        s += __shfl_xor_sync(0xffffffffu, s, o);
        q += __shfl_xor_sync(0xffffffffu, q, o);
    }
    mean = s * (1.0f / DD);
    float var = q * (1.0f / DD) - mean * mean;
    rstd = rsqrtf(var + LN_EPS);
}

// -------- block LayerNorm over 128 threads (embed kernel only) --------
__device__ __forceinline__ void ln_stats_128(float y, float& mean, float& rstd) {
    __shared__ float sh[8];
    float s = y, q = y * y;
#pragma unroll
    for (int o = 16; o > 0; o >>= 1) {
        s += __shfl_xor_sync(0xffffffffu, s, o);
        q += __shfl_xor_sync(0xffffffffu, q, o);
    }
    int lane = threadIdx.x & 31, w = threadIdx.x >> 5;
    if (lane == 0) { sh[w] = s; sh[4 + w] = q; }
    __syncthreads();
    s = sh[0] + sh[1] + sh[2] + sh[3];
    q = sh[4] + sh[5] + sh[6] + sh[7];
    mean = s * (1.0f / DD);
    float var = q * (1.0f / DD) - mean * mean;
    rstd = rsqrtf(var + LN_EPS);
}

// -------- embed + LN:  h = LN(x @ We + be) --------
__global__ void __launch_bounds__(128)
embed_ln_kernel(const float* __restrict__ x, const float* __restrict__ We,
                const float* __restrict__ be, const float* __restrict__ ge,
                const float* __restrict__ bge) {
    int t = blockIdx.x, d = threadIdx.x;
    float x0 = x[t * 2 + 0];
    float x1 = x[t * 2 + 1];
    float y = fmaf(x0, We[d], fmaf(x1, We[DD + d], be[d]));
    float mean, rstd;
    ln_stats_128(y, mean, rstd);
    g_h[t * DD + d] = (y - mean) * rstd * ge[d] + bge[d];
}

// -------- per-batch per-feature (max1, max2, argmax) over the N=256 set --------
// grid(8), block(128 d x 4 splits). 4-way split scan + smem merge.
__global__ void __launch_bounds__(512)
stats_kernel() {
    int b = blockIdx.x;
    int d = threadIdx.x;
    int s = threadIdx.y;
    const float* hb = g_h + b * NN * DD;

    float m1 = NEG_INF, m2 = NEG_INF;
    int i1 = 0;
    int n0 = s * (NN / 4);
#pragma unroll 8
    for (int n = n0; n < n0 + NN / 4; n++) {
        float v = hb[n * DD + d];
        if (v > m1) { m2 = m1; m1 = v; i1 = n; }
        else if (v > m2) { m2 = v; }
    }
    __shared__ float sm1[4][DD], sm2[4][DD];
    __shared__ int si1[4][DD];
    sm1[s][d] = m1; sm2[s][d] = m2; si1[s][d] = i1;
    __syncthreads();
    if (s == 0) {
#pragma unroll
        for (int j = 1; j < 4; j++) {
            float a1 = sm1[j][d], a2 = sm2[j][d];
            int ai = si1[j][d];
            if (a1 > m1) { m2 = fmaxf(m1, a2); m1 = a1; i1 = ai; }
            else         { m2 = fmaxf(m2, a1); }
        }
        g_m1[b * DD + d] = m1;
        g_m2[b * DD + d] = m2;
        g_i1[b * DD + d] = i1;
    }
}

// -------- pool GEMM (+residual+LN fused):  h = LN(h + [h,loo(h)] @ Wp + bp) --------
// Block (32,8) covers 16 tokens x all 128 cols. K=256: first 128 = h,
// second 128 = pooled, synthesized on the fly from (m1,m2,i1).
// Warp ty owns complete rows {ty, ty+8} -> LN via warp shuffle, no extra sync.
__global__ void __launch_bounds__(256)
pool_gemm_ln_kernel(const float* __restrict__ Wp, const float* __restrict__ bp,
                    const float* __restrict__ gp, const float* __restrict__ bgp) {
    __shared__ float As[16][32];
    __shared__ float Ws[32][DD];
    __shared__ float sm1[DD], sm2[DD];
    __shared__ int   si1[DD];

    const int tx = threadIdx.x, ty = threadIdx.y;
    const int tid = ty * 32 + tx;
    const int row0 = blockIdx.x * 16;
    const int b = row0 >> 8;          // 256 tokens per batch, 16 | 256
    const int nbase = row0 & 255;     // n-offset within batch

    if (tid < DD) {
        sm1[tid] = g_m1[b * DD + tid];
        sm2[tid] = g_m2[b * DD + tid];
        si1[tid] = g_i1[b * DD + tid];
    }

    float acc[2][4];
#pragma unroll
    for (int r = 0; r < 2; r++)
#pragma unroll
        for (int c = 0; c < 4; c++) acc[r][c] = 0.0f;

    for (int k0 = 0; k0 < 2 * DD; k0 += 32) {
        __syncthreads();   // prior tile consumed; also covers stats-load at k0=0
        // A tile 16x32: top half from g_h, bottom half synthesized pooled values
#pragma unroll
        for (int i = tid; i < 16 * 32; i += 256) {
            int r = i >> 5, cc = i & 31;
            int k = k0 + cc;
            float v;
            if (k < DD) {
                v = g_h[(row0 + r) * DD + k];
            } else {
                int kk = k - DD;
                v = (nbase + r == si1[kk]) ? sm2[kk] : sm1[kk];
            }
            As[r][cc] = v;
        }
        // W tile 32x128, coalesced
#pragma unroll
        for (int i = tid; i < 32 * DD; i += 256) {
            int r = i >> 7, cc = i & 127;
            Ws[r][cc] = Wp[(k0 + r) * DD + cc];
        }
        __syncthreads();

        float areg[2][32];
#pragma unroll
        for (int r = 0; r < 2; r++)
#pragma unroll
            for (int kk = 0; kk < 32; kk += 4) {
                float4 v = *reinterpret_cast<const float4*>(&As[ty + r * 8][kk]);
                areg[r][kk + 0] = v.x; areg[r][kk + 1] = v.y;
                areg[r][kk + 2] = v.z; areg[r][kk + 3] = v.w;
            }
#pragma unroll
        for (int kk = 0; kk < 32; kk++) {
            float w[4];
#pragma unroll
            for (int c = 0; c < 4; c++) w[c] = Ws[kk][tx + c * 32];
#pragma unroll
            for (int r = 0; r < 2; r++)
#pragma unroll
                for (int c = 0; c < 4; c++)
                    acc[r][c] = fmaf(areg[r][kk], w[c], acc[r][c]);
        }
    }

    // epilogue: +bias, +residual h, LN per row (warp-local), write back to g_h
#pragma unroll
    for (int rr = 0; rr < 2; rr++) {
        int row = row0 + ty + rr * 8;
        float v[4], s = 0.0f, q = 0.0f;
#pragma unroll
        for (int c = 0; c < 4; c++) {
            int col = tx + c * 32;
            v[c] = acc[rr][c] + bp[col] + g_h[row * DD + col];
            s += v[c];
            q += v[c] * v[c];
        }
        float mean, rstd;
        warp_ln_stats(s, q, mean, rstd);
#pragma unroll
        for (int c = 0; c < 4; c++) {
            int col = tx + c * 32;
            g_h[row * DD + col] = (v[c] - mean) * rstd * gp[col] + bgp[col];
        }
    }
}

// -------- fused FF:  h' = LN(h + relu(h@W1+b1)@W2 + b2) --------
// Block (32,8) covers 16 tokens. H=512 streamed in 4 chunks of 128 through smem:
// hs 8KB | W1c 64KB | W2c 64KB | Us 8KB = 144KB dynamic smem. ff1 output never
// leaves the SM. Warp-local LN epilogue; residual comes from hs (free).
#define FF_CH 128
template <bool FINAL>
__global__ void __launch_bounds__(256)
ff_fused_kernel(const float* __restrict__ W1, const float* __restrict__ b1,
                const float* __restrict__ W2, const float* __restrict__ b2,
                const float* __restrict__ gf, const float* __restrict__ bgf,
                float* __restrict__ out) {
    extern __shared__ float smem[];
    float (*hs)[DD]     = reinterpret_cast<float (*)[DD]>(smem);                    // 16x128
    float (*W1c)[FF_CH] = reinterpret_cast<float (*)[FF_CH]>(smem + 16 * DD);       // 128x128
    float (*W2c)[DD]    = reinterpret_cast<float (*)[DD]>(smem + 16 * DD + DD * FF_CH);
    float (*Us)[FF_CH]  = reinterpret_cast<float (*)[FF_CH]>(smem + 16 * DD + 2 * DD * FF_CH);

    const int tx = threadIdx.x, ty = threadIdx.y;
    const int tid = ty * 32 + tx;
    const int row0 = blockIdx.x * 16;

    // load h rows once (also serves as the residual later)
#pragma unroll
    for (int i = tid; i < 16 * DD; i += 256)
        hs[i >> 7][i & 127] = g_h[row0 * DD + i];

    float acc2[2][4];
#pragma unroll
    for (int r = 0; r < 2; r++)
#pragma unroll
        for (int c = 0; c < 4; c++) acc2[r][c] = 0.0f;

    for (int c0 = 0; c0 < HH; c0 += FF_CH) {
        __syncthreads();   // hs ready (1st iter) / W,Us consumed (later iters)
        // load W1 chunk (128 x 128) and W2 chunk (128 x 128), coalesced
#pragma unroll
        for (int i = tid; i < DD * FF_CH; i += 256) {
            int k = i >> 7, cc = i & 127;
            W1c[k][cc] = W1[k * HH + c0 + cc];
        }
#pragma unroll
        for (int i = tid; i < FF_CH * DD; i += 256) {
            int k = i >> 7, cc = i & 127;
            W2c[k][cc] = W2[(c0 + k) * DD + cc];
        }
        __syncthreads();

        // ---- ff1: U = relu(hs @ W1c + b1[c0:]) ----
        float acc1[2][4];
#pragma unroll
        for (int r = 0; r < 2; r++)
#pragma unroll
            for (int c = 0; c < 4; c++) acc1[r][c] = 0.0f;

        for (int kk0 = 0; kk0 < DD; kk0 += 16) {
            float areg[2][16];
#pragma unroll
            for (int r = 0; r < 2; r++)
#pragma unroll
                for (int kk = 0; kk < 16; kk += 4) {
                    float4 v = *reinterpret_cast<const float4*>(&hs[ty + r * 8][kk0 + kk]);
                    areg[r][kk + 0] = v.x; areg[r][kk + 1] = v.y;
                    areg[r][kk + 2] = v.z; areg[r][kk + 3] = v.w;
                }
#pragma unroll
            for (int kk = 0; kk < 16; kk++) {
                float w[4];
#pragma unroll
                for (int c = 0; c < 4; c++) w[c] = W1c[kk0 + kk][tx + c * 32];
#pragma unroll
                for (int r = 0; r < 2; r++)
#pragma unroll
                    for (int c = 0; c < 4; c++)
                        acc1[r][c] = fmaf(areg[r][kk], w[c], acc1[r][c]);
            }
        }
#pragma unroll
        for (int r = 0; r < 2; r++)
#pragma unroll
            for (int c = 0; c < 4; c++) {
                int col = tx + c * 32;
                Us[ty + r * 8][col] = fmaxf(acc1[r][c] + b1[c0 + col], 0.0f);
            }
        __syncthreads();

        // ---- ff2 partial: acc2 += Us @ W2c ----
        for (int kk0 = 0; kk0 < FF_CH; kk0 += 16) {
            float areg[2][16];
#pragma unroll
            for (int r = 0; r < 2; r++)
#pragma unroll
                for (int kk = 0; kk < 16; kk += 4) {
                    float4 v = *reinterpret_cast<const float4*>(&Us[ty + r * 8][kk0 + kk]);
                    areg[r][kk + 0] = v.x; areg[r][kk + 1] = v.y;
                    areg[r][kk + 2] = v.z; areg[r][kk + 3] = v.w;
                }
#pragma unroll
            for (int kk = 0; kk < 16; kk++) {
                float w[4];
#pragma unroll
                for (int c = 0; c < 4; c++) w[c] = W2c[kk0 + kk][tx + c * 32];
#pragma unroll
                for (int r = 0; r < 2; r++)
#pragma unroll
                    for (int c = 0; c < 4; c++)
                        acc2[r][c] = fmaf(areg[r][kk], w[c], acc2[r][c]);
            }
        }
    }

    // epilogue: +b2, +residual (hs), LN per row (warp-local)
#pragma unroll
    for (int rr = 0; rr < 2; rr++) {
        int r = ty + rr * 8;
        int row = row0 + r;
        float v[4], s = 0.0f, q = 0.0f;
#pragma unroll
        for (int c = 0; c < 4; c++) {
            int col = tx + c * 32;
            v[c] = acc2[rr][c] + b2[col] + hs[r][col];
            s += v[c];
            q += v[c] * v[c];
        }
        float mean, rstd;
        warp_ln_stats(s, q, mean, rstd);
#pragma unroll
        for (int c = 0; c < 4; c++) {
            int col = tx + c * 32;
            float rv = (v[c] - mean) * rstd * gf[col] + bgf[col];
            if (FINAL) out[row * DD + col] = rv;
            else       g_h[row * DD + col] = rv;
        }
    }
}

extern "C" void kernel_launch(void* const* d_in, const int* in_sizes, int n_in,
                              void* d_out, int out_size) {
    const float* x   = (const float*)d_in[0];   // (8,256,2)
    const float* We  = (const float*)d_in[1];   // (2,128)
    const float* be  = (const float*)d_in[2];
    const float* ge  = (const float*)d_in[3];
    const float* bge = (const float*)d_in[4];
    const float* Wp  = (const float*)d_in[5];   // (2,256,128)
    const float* bp  = (const float*)d_in[6];
    const float* gp  = (const float*)d_in[7];
    const float* bgp = (const float*)d_in[8];
    const float* W1  = (const float*)d_in[9];   // (2,128,512)
    const float* b1  = (const float*)d_in[10];
    const float* W2  = (const float*)d_in[11];  // (2,512,128)
    const float* b2  = (const float*)d_in[12];
    const float* gf  = (const float*)d_in[13];
    const float* bgf = (const float*)d_in[14];
    float* out = (float*)d_out;                 // (8,256,128) fp32

    constexpr int FF_SMEM = (16 * DD + 2 * DD * FF_CH + 16 * FF_CH) * 4;  // 147456 B
    cudaFuncSetAttribute(ff_fused_kernel<false>,
                         cudaFuncAttributeMaxDynamicSharedMemorySize, FF_SMEM);
    cudaFuncSetAttribute(ff_fused_kernel<true>,
                         cudaFuncAttributeMaxDynamicSharedMemorySize, FF_SMEM);

    embed_ln_kernel<<<T_TOK, 128>>>(x, We, be, ge, bge);

    for (int i = 0; i < 2; i++) {
        stats_kernel<<<NB, dim3(128, 4)>>>();

        pool_gemm_ln_kernel<<<T_TOK / 16, dim3(32, 8)>>>(
            Wp + i * 2 * DD * DD, bp + i * DD, gp + i * DD, bgp + i * DD);

        if (i == 1)
            ff_fused_kernel<true><<<T_TOK / 16, dim3(32, 8), FF_SMEM>>>(
                W1 + i * DD * HH, b1 + i * HH, W2 + i * HH * DD, b2 + i * DD,
                gf + i * DD, bgf + i * DD, out);
        else
            ff_fused_kernel<false><<<T_TOK / 16, dim3(32, 8), FF_SMEM>>>(
                W1 + i * DD * HH, b1 + i * HH, W2 + i * HH * DD, b2 + i * DD,
                gf + i * DD, bgf + i * DD, nullptr);
    }
}

// round 6
// speedup vs baseline: 2.1065x; 1.6095x over previous
#include <cuda_runtime.h>

// PermutationInvariantNet: B=8, N=256, IN_DIM=2, D=128, H=512, L=2
// Tokens T = B*N = 2048. All fp32.
// 7-launch graph: embed, 2x { stats, pool_gemm+LN, ff(ff1+relu+ff2+res+LN) }.
// GEMM cores: one warp per token row, lanes own 4 contiguous cols ->
// LDS.128 fragments, warp-shuffle LayerNorm epilogues.

#define T_TOK 2048
#define NB 8
#define NN 256
#define DD 128
#define HH 512
#define FF_CH 128
#define TMF 16
#define LN_EPS 1e-5f
#define NEG_INF -3.402823466e38f

// -------- scratch (device globals; no allocation allowed) --------
__device__ __align__(16) float g_h[T_TOK * DD];   // hidden state (1 MB)
__device__ float g_m1[NB * DD];                   // per-batch per-feature max
__device__ float g_m2[NB * DD];                   // second max
__device__ int   g_i1[NB * DD];                   // argmax (n within batch)

// -------- warp-local LayerNorm stats (row fully owned by one warp) --------
__device__ __forceinline__ void warp_ln_stats(float s, float q, float& mean, float& rstd) {
#pragma unroll
    for (int o = 16; o > 0; o >>= 1) {
        s += __shfl_xor_sync(0xffffffffu, s, o);
        q += __shfl_xor_sync(0xffffffffu, q, o);
    }
    mean = s * (1.0f / DD);
    float var = q * (1.0f / DD) - mean * mean;
    rstd = rsqrtf(var + LN_EPS);
}

// -------- block LayerNorm over 128 threads (embed kernel only) --------
__device__ __forceinline__ void ln_stats_128(float y, float& mean, float& rstd) {
    __shared__ float sh[8];
    float s = y, q = y * y;
#pragma unroll
    for (int o = 16; o > 0; o >>= 1) {
        s += __shfl_xor_sync(0xffffffffu, s, o);
        q += __shfl_xor_sync(0xffffffffu, q, o);
    }
    int lane = threadIdx.x & 31, w = threadIdx.x >> 5;
    if (lane == 0) { sh[w] = s; sh[4 + w] = q; }
    __syncthreads();
    s = sh[0] + sh[1] + sh[2] + sh[3];
    q = sh[4] + sh[5] + sh[6] + sh[7];
    mean = s * (1.0f / DD);
    float var = q * (1.0f / DD) - mean * mean;
    rstd = rsqrtf(var + LN_EPS);
}

// -------- embed + LN:  h = LN(x @ We + be) --------
__global__ void __launch_bounds__(128)
embed_ln_kernel(const float* __restrict__ x, const float* __restrict__ We,
                const float* __restrict__ be, const float* __restrict__ ge,
                const float* __restrict__ bge) {
    int t = blockIdx.x, d = threadIdx.x;
    float x0 = x[t * 2 + 0];
    float x1 = x[t * 2 + 1];
    float y = fmaf(x0, We[d], fmaf(x1, We[DD + d], be[d]));
    float mean, rstd;
    ln_stats_128(y, mean, rstd);
    g_h[t * DD + d] = (y - mean) * rstd * ge[d] + bge[d];
}

// -------- per-batch per-feature (max1, max2, argmax) over the N=256 set --------
__global__ void __launch_bounds__(512)
stats_kernel() {
    int b = blockIdx.x;
    int d = threadIdx.x;
    int s = threadIdx.y;
    const float* hb = g_h + b * NN * DD;

    float m1 = NEG_INF, m2 = NEG_INF;
    int i1 = 0;
    int n0 = s * (NN / 4);
#pragma unroll 8
    for (int n = n0; n < n0 + NN / 4; n++) {
        float v = hb[n * DD + d];
        if (v > m1) { m2 = m1; m1 = v; i1 = n; }
        else if (v > m2) { m2 = v; }
    }
    __shared__ float sm1[4][DD], sm2[4][DD];
    __shared__ int si1[4][DD];
    sm1[s][d] = m1; sm2[s][d] = m2; si1[s][d] = i1;
    __syncthreads();
    if (s == 0) {
#pragma unroll
        for (int j = 1; j < 4; j++) {
            float a1 = sm1[j][d], a2 = sm2[j][d];
            int ai = si1[j][d];
            if (a1 > m1) { m2 = fmaxf(m1, a2); m1 = a1; i1 = ai; }
            else         { m2 = fmaxf(m2, a1); }
        }
        g_m1[b * DD + d] = m1;
        g_m2[b * DD + d] = m2;
        g_i1[b * DD + d] = i1;
    }
}

// -------- pool GEMM (+res+LN):  h = LN(h + [h, loo(h)] @ Wp + bp) --------
// grid 128, block (32,16): warp ty owns token row0+ty; lane owns cols tx*4..+3.
// K=256 in 8 tiles of 32; pooled half (k>=128) synthesized from (m1,m2,i1).
__global__ void __launch_bounds__(512, 1)
pool_gemm_ln_kernel(const float* __restrict__ Wp, const float* __restrict__ bp,
                    const float* __restrict__ gp, const float* __restrict__ bgp) {
    __shared__ __align__(16) float As[TMF][32];
    __shared__ __align__(16) float Ws[32][DD];
    __shared__ float sm1[DD], sm2[DD];
    __shared__ int   si1[DD];

    const int tx = threadIdx.x, ty = threadIdx.y;
    const int tid = ty * 32 + tx;
    const int row0 = blockIdx.x * TMF;
    const int b = row0 >> 8;
    const int nbase = row0 & 255;
    const int c4 = tx * 4;

    if (tid < DD) {
        sm1[tid] = g_m1[b * DD + tid];
        sm2[tid] = g_m2[b * DD + tid];
        si1[tid] = g_i1[b * DD + tid];
    }

    float acc[4] = {0.f, 0.f, 0.f, 0.f};

    for (int k0 = 0; k0 < 2 * DD; k0 += 32) {
        __syncthreads();   // prior tile consumed; first iter covers stats-load
        // A tile 16x32: one element per thread
        {
            int r = tid >> 5, cc = tid & 31;
            int k = k0 + cc;
            float v;
            if (k < DD) {
                v = g_h[(row0 + r) * DD + k];
            } else {
                int kk = k - DD;
                v = (nbase + r == si1[kk]) ? sm2[kk] : sm1[kk];
            }
            As[r][cc] = v;
        }
        // W tile 32x128: 2 float4 per thread, coalesced
#pragma unroll
        for (int i = tid * 4; i < 32 * DD; i += 512 * 4) {
            int r = i >> 7, cc = i & 127;
            *reinterpret_cast<float4*>(&Ws[r][cc]) =
                *reinterpret_cast<const float4*>(&Wp[(k0 + r) * DD + cc]);
        }
        __syncthreads();

#pragma unroll 8
        for (int kk0 = 0; kk0 < 32; kk0 += 4) {
            float4 a = *reinterpret_cast<const float4*>(&As[ty][kk0]);
            float4 w;
            w = *reinterpret_cast<const float4*>(&Ws[kk0 + 0][c4]);
            acc[0] = fmaf(a.x, w.x, acc[0]); acc[1] = fmaf(a.x, w.y, acc[1]);
            acc[2] = fmaf(a.x, w.z, acc[2]); acc[3] = fmaf(a.x, w.w, acc[3]);
            w = *reinterpret_cast<const float4*>(&Ws[kk0 + 1][c4]);
            acc[0] = fmaf(a.y, w.x, acc[0]); acc[1] = fmaf(a.y, w.y, acc[1]);
            acc[2] = fmaf(a.y, w.z, acc[2]); acc[3] = fmaf(a.y, w.w, acc[3]);
            w = *reinterpret_cast<const float4*>(&Ws[kk0 + 2][c4]);
            acc[0] = fmaf(a.z, w.x, acc[0]); acc[1] = fmaf(a.z, w.y, acc[1]);
            acc[2] = fmaf(a.z, w.z, acc[2]); acc[3] = fmaf(a.z, w.w, acc[3]);
            w = *reinterpret_cast<const float4*>(&Ws[kk0 + 3][c4]);
            acc[0] = fmaf(a.w, w.x, acc[0]); acc[1] = fmaf(a.w, w.y, acc[1]);
            acc[2] = fmaf(a.w, w.z, acc[2]); acc[3] = fmaf(a.w, w.w, acc[3]);
        }
    }

    // epilogue: +bias, +residual, warp LN, write back
    int row = row0 + ty;
    float v[4], s = 0.0f, q = 0.0f;
#pragma unroll
    for (int c = 0; c < 4; c++) {
        v[c] = acc[c] + bp[c4 + c] + g_h[row * DD + c4 + c];
        s += v[c];
        q += v[c] * v[c];
    }
    float mean, rstd;
    warp_ln_stats(s, q, mean, rstd);
    float4 o;
    o.x = (v[0] - mean) * rstd * gp[c4 + 0] + bgp[c4 + 0];
    o.y = (v[1] - mean) * rstd * gp[c4 + 1] + bgp[c4 + 1];
    o.z = (v[2] - mean) * rstd * gp[c4 + 2] + bgp[c4 + 2];
    o.w = (v[3] - mean) * rstd * gp[c4 + 3] + bgp[c4 + 3];
    *reinterpret_cast<float4*>(&g_h[row * DD + c4]) = o;
}

// -------- fused FF:  h' = LN(h + relu(h@W1+b1)@W2 + b2) --------
// grid 128, block (32,16) = 16 warps; warp ty owns token row0+ty, lane owns
// cols tx*4..+3. H streamed in 4 chunks of 128 through 144KB dynamic smem.
template <bool FINAL>
__global__ void __launch_bounds__(512, 1)
ff_fused_kernel(const float* __restrict__ W1, const float* __restrict__ b1,
                const float* __restrict__ W2, const float* __restrict__ b2,
                const float* __restrict__ gf, const float* __restrict__ bgf,
                float* __restrict__ out) {
    extern __shared__ float smem[];
    float (*hs)[DD]     = reinterpret_cast<float (*)[DD]>(smem);                 // 16x128
    float (*W1c)[FF_CH] = reinterpret_cast<float (*)[FF_CH]>(smem + TMF * DD);   // 128x128
    float (*W2c)[DD]    = reinterpret_cast<float (*)[DD]>(smem + TMF * DD + DD * FF_CH);
    float (*Us)[FF_CH]  = reinterpret_cast<float (*)[FF_CH]>(smem + TMF * DD + 2 * DD * FF_CH);

    const int tx = threadIdx.x, ty = threadIdx.y;
    const int tid = ty * 32 + tx;
    const int row0 = blockIdx.x * TMF;
    const int c4 = tx * 4;

    // load h rows once (doubles as the residual)
    {
        int i = tid * 4;
        *reinterpret_cast<float4*>(&hs[i >> 7][i & 127]) =
            *reinterpret_cast<const float4*>(&g_h[row0 * DD + i]);
    }

    float acc2[4] = {0.f, 0.f, 0.f, 0.f};

    for (int c0 = 0; c0 < HH; c0 += FF_CH) {
        __syncthreads();   // hs ready (1st iter) / W,Us consumed (later iters)
        // load W1 chunk (128x128) and W2 chunk (128x128): 8 float4 each/thread
#pragma unroll
        for (int i = tid * 4; i < DD * FF_CH; i += 512 * 4) {
            int k = i >> 7, cc = i & 127;
            *reinterpret_cast<float4*>(&W1c[k][cc]) =
                *reinterpret_cast<const float4*>(&W1[k * HH + c0 + cc]);
        }
#pragma unroll
        for (int i = tid * 4; i < FF_CH * DD; i += 512 * 4) {
            int k = i >> 7, cc = i & 127;
            *reinterpret_cast<float4*>(&W2c[k][cc]) =
                *reinterpret_cast<const float4*>(&W2[(c0 + k) * DD + cc]);
        }
        __syncthreads();

        // ---- ff1: Us[ty][c4..] = relu(hs[ty] . W1c[:, c4..] + b1) ----
        float acc1[4] = {0.f, 0.f, 0.f, 0.f};
#pragma unroll 8
        for (int kk0 = 0; kk0 < DD; kk0 += 4) {
            float4 a = *reinterpret_cast<const float4*>(&hs[ty][kk0]);
            float4 w;
            w = *reinterpret_cast<const float4*>(&W1c[kk0 + 0][c4]);
            acc1[0] = fmaf(a.x, w.x, acc1[0]); acc1[1] = fmaf(a.x, w.y, acc1[1]);
            acc1[2] = fmaf(a.x, w.z, acc1[2]); acc1[3] = fmaf(a.x, w.w, acc1[3]);
            w = *reinterpret_cast<const float4*>(&W1c[kk0 + 1][c4]);
            acc1[0] = fmaf(a.y, w.x, acc1[0]); acc1[1] = fmaf(a.y, w.y, acc1[1]);
            acc1[2] = fmaf(a.y, w.z, acc1[2]); acc1[3] = fmaf(a.y, w.w, acc1[3]);
            w = *reinterpret_cast<const float4*>(&W1c[kk0 + 2][c4]);
            acc1[0] = fmaf(a.z, w.x, acc1[0]); acc1[1] = fmaf(a.z, w.y, acc1[1]);
            acc1[2] = fmaf(a.z, w.z, acc1[2]); acc1[3] = fmaf(a.z, w.w, acc1[3]);
            w = *reinterpret_cast<const float4*>(&W1c[kk0 + 3][c4]);
            acc1[0] = fmaf(a.w, w.x, acc1[0]); acc1[1] = fmaf(a.w, w.y, acc1[1]);
            acc1[2] = fmaf(a.w, w.z, acc1[2]); acc1[3] = fmaf(a.w, w.w, acc1[3]);
        }
        {
            float4 u;
            u.x = fmaxf(acc1[0] + b1[c0 + c4 + 0], 0.0f);
            u.y = fmaxf(acc1[1] + b1[c0 + c4 + 1], 0.0f);
            u.z = fmaxf(acc1[2] + b1[c0 + c4 + 2], 0.0f);
            u.w = fmaxf(acc1[3] + b1[c0 + c4 + 3], 0.0f);
            *reinterpret_cast<float4*>(&Us[ty][c4]) = u;
        }
        __syncthreads();

        // ---- ff2 partial: acc2 += Us[ty] . W2c[:, c4..] ----
#pragma unroll 8
        for (int kk0 = 0; kk0 < FF_CH; kk0 += 4) {
            float4 a = *reinterpret_cast<const float4*>(&Us[ty][kk0]);
            float4 w;
            w = *reinterpret_cast<const float4*>(&W2c[kk0 + 0][c4]);
            acc2[0] = fmaf(a.x, w.x, acc2[0]); acc2[1] = fmaf(a.x, w.y, acc2[1]);
            acc2[2] = fmaf(a.x, w.z, acc2[2]); acc2[3] = fmaf(a.x, w.w, acc2[3]);
            w = *reinterpret_cast<const float4*>(&W2c[kk0 + 1][c4]);
            acc2[0] = fmaf(a.y, w.x, acc2[0]); acc2[1] = fmaf(a.y, w.y, acc2[1]);
            acc2[2] = fmaf(a.y, w.z, acc2[2]); acc2[3] = fmaf(a.y, w.w, acc2[3]);
            w = *reinterpret_cast<const float4*>(&W2c[kk0 + 2][c4]);
            acc2[0] = fmaf(a.z, w.x, acc2[0]); acc2[1] = fmaf(a.z, w.y, acc2[1]);
            acc2[2] = fmaf(a.z, w.z, acc2[2]); acc2[3] = fmaf(a.z, w.w, acc2[3]);
            w = *reinterpret_cast<const float4*>(&W2c[kk0 + 3][c4]);
            acc2[0] = fmaf(a.w, w.x, acc2[0]); acc2[1] = fmaf(a.w, w.y, acc2[1]);
            acc2[2] = fmaf(a.w, w.z, acc2[2]); acc2[3] = fmaf(a.w, w.w, acc2[3]);
        }
    }

    // epilogue: +b2, +residual (hs), warp LN
    int row = row0 + ty;
    float v[4], s = 0.0f, q = 0.0f;
#pragma unroll
    for (int c = 0; c < 4; c++) {
        v[c] = acc2[c] + b2[c4 + c] + hs[ty][c4 + c];
        s += v[c];
        q += v[c] * v[c];
    }
    float mean, rstd;
    warp_ln_stats(s, q, mean, rstd);
    float4 o;
    o.x = (v[0] - mean) * rstd * gf[c4 + 0] + bgf[c4 + 0];
    o.y = (v[1] - mean) * rstd * gf[c4 + 1] + bgf[c4 + 1];
    o.z = (v[2] - mean) * rstd * gf[c4 + 2] + bgf[c4 + 2];
    o.w = (v[3] - mean) * rstd * gf[c4 + 3] + bgf[c4 + 3];
    if (FINAL) *reinterpret_cast<float4*>(&out[row * DD + c4]) = o;
    else       *reinterpret_cast<float4*>(&g_h[row * DD + c4]) = o;
}

extern "C" void kernel_launch(void* const* d_in, const int* in_sizes, int n_in,
                              void* d_out, int out_size) {
    const float* x   = (const float*)d_in[0];   // (8,256,2)
    const float* We  = (const float*)d_in[1];   // (2,128)
    const float* be  = (const float*)d_in[2];
    const float* ge  = (const float*)d_in[3];
    const float* bge = (const float*)d_in[4];
    const float* Wp  = (const float*)d_in[5];   // (2,256,128)
    const float* bp  = (const float*)d_in[6];
    const float* gp  = (const float*)d_in[7];
    const float* bgp = (const float*)d_in[8];
    const float* W1  = (const float*)d_in[9];   // (2,128,512)
    const float* b1  = (const float*)d_in[10];
    const float* W2  = (const float*)d_in[11];  // (2,512,128)
    const float* b2  = (const float*)d_in[12];
    const float* gf  = (const float*)d_in[13];
    const float* bgf = (const float*)d_in[14];
    float* out = (float*)d_out;                 // (8,256,128) fp32

    constexpr int FF_SMEM = (TMF * DD + 2 * DD * FF_CH + TMF * FF_CH) * 4;  // 147456 B
    cudaFuncSetAttribute(ff_fused_kernel<false>,
                         cudaFuncAttributeMaxDynamicSharedMemorySize, FF_SMEM);
    cudaFuncSetAttribute(ff_fused_kernel<true>,
                         cudaFuncAttributeMaxDynamicSharedMemorySize, FF_SMEM);

    embed_ln_kernel<<<T_TOK, 128>>>(x, We, be, ge, bge);

    for (int i = 0; i < 2; i++) {
        stats_kernel<<<NB, dim3(128, 4)>>>();

        pool_gemm_ln_kernel<<<T_TOK / TMF, dim3(32, 16)>>>(
            Wp + i * 2 * DD * DD, bp + i * DD, gp + i * DD, bgp + i * DD);

        if (i == 1)
            ff_fused_kernel<true><<<T_TOK / TMF, dim3(32, 16), FF_SMEM>>>(
                W1 + i * DD * HH, b1 + i * HH, W2 + i * HH * DD, b2 + i * DD,
                gf + i * DD, bgf + i * DD, out);
        else
            ff_fused_kernel<false><<<T_TOK / TMF, dim3(32, 16), FF_SMEM>>>(
                W1 + i * DD * HH, b1 + i * HH, W2 + i * HH * DD, b2 + i * DD,
                gf + i * DD, bgf + i * DD, nullptr);
    }
}

// round 7
// speedup vs baseline: 4.1883x; 1.9883x over previous
#include <cuda_runtime.h>
#include <cstdint>

// PermutationInvariantNet: B=8, N=256, IN_DIM=2, D=128, H=512, L=2
// Tokens T = B*N = 2048. fp32.
// 7 launches: embed, 2x { stats, pool_gemm+LN, ff(ff1+relu+ff2+res+LN) }.
// GEMM cores: RR=4 register blocking (thread = 4 rows x 2 cols), cp.async
// weight pipelining, warp+smem LayerNorm epilogues.

#define T_TOK 2048
#define NB 8
#define NN 256
#define DD 128
#define HH 512
#define LN_EPS 1e-5f
#define NEG_INF -3.402823466e38f

// -------- scratch (device globals; no allocation allowed) --------
__device__ __align__(16) float g_h[T_TOK * DD];   // hidden state (1 MB)
__device__ float g_m1[NB * DD];                   // per-batch per-feature max
__device__ float g_m2[NB * DD];                   // second max
__device__ int   g_i1[NB * DD];                   // argmax (n within batch)

// -------- cp.async helpers --------
__device__ __forceinline__ void cp_async16(uint32_t dst, const void* src) {
    asm volatile("cp.async.cg.shared.global [%0], [%1], 16;" :: "r"(dst), "l"(src));
}
__device__ __forceinline__ void cp_commit() {
    asm volatile("cp.async.commit_group;");
}
__device__ __forceinline__ void cp_wait1() {
    asm volatile("cp.async.wait_group 1;");
}
__device__ __forceinline__ void cp_wait0() {
    asm volatile("cp.async.wait_group 0;");
}

// -------- block LayerNorm over 128 threads (embed kernel only) --------
__device__ __forceinline__ void ln_stats_128(float y, float& mean, float& rstd) {
    __shared__ float sh[8];
    float s = y, q = y * y;
#pragma unroll
    for (int o = 16; o > 0; o >>= 1) {
        s += __shfl_xor_sync(0xffffffffu, s, o);
        q += __shfl_xor_sync(0xffffffffu, q, o);
    }
    int lane = threadIdx.x & 31, w = threadIdx.x >> 5;
    if (lane == 0) { sh[w] = s; sh[4 + w] = q; }
    __syncthreads();
    s = sh[0] + sh[1] + sh[2] + sh[3];
    q = sh[4] + sh[5] + sh[6] + sh[7];
    mean = s * (1.0f / DD);
    float var = q * (1.0f / DD) - mean * mean;
    rstd = rsqrtf(var + LN_EPS);
}

// -------- embed + LN:  h = LN(x @ We + be) --------
__global__ void __launch_bounds__(128)
embed_ln_kernel(const float* __restrict__ x, const float* __restrict__ We,
                const float* __restrict__ be, const float* __restrict__ ge,
                const float* __restrict__ bge) {
    int t = blockIdx.x, d = threadIdx.x;
    float x0 = x[t * 2 + 0];
    float x1 = x[t * 2 + 1];
    float y = fmaf(x0, We[d], fmaf(x1, We[DD + d], be[d]));
    float mean, rstd;
    ln_stats_128(y, mean, rstd);
    g_h[t * DD + d] = (y - mean) * rstd * ge[d] + bge[d];
}

// -------- per-batch per-feature (max1, max2, argmax) over N=256 --------
__global__ void __launch_bounds__(512)
stats_kernel() {
    int b = blockIdx.x;
    int d = threadIdx.x;
    int s = threadIdx.y;
    const float* hb = g_h + b * NN * DD;

    float m1 = NEG_INF, m2 = NEG_INF;
    int i1 = 0;
    int n0 = s * (NN / 4);
#pragma unroll 8
    for (int n = n0; n < n0 + NN / 4; n++) {
        float v = hb[n * DD + d];
        if (v > m1) { m2 = m1; m1 = v; i1 = n; }
        else if (v > m2) { m2 = v; }
    }
    __shared__ float sm1[4][DD], sm2[4][DD];
    __shared__ int si1[4][DD];
    sm1[s][d] = m1; sm2[s][d] = m2; si1[s][d] = i1;
    __syncthreads();
    if (s == 0) {
#pragma unroll
        for (int j = 1; j < 4; j++) {
            float a1 = sm1[j][d], a2 = sm2[j][d];
            int ai = si1[j][d];
            if (a1 > m1) { m2 = fmaxf(m1, a2); m1 = a1; i1 = ai; }
            else         { m2 = fmaxf(m2, a1); }
        }
        g_m1[b * DD + d] = m1;
        g_m2[b * DD + d] = m2;
        g_i1[b * DD + d] = i1;
    }
}

// ===================== pool GEMM (+res+LN) =====================
// h = LN(h + [h, loo(h)] @ Wp + bp). Block: 256 thr = 8 warps =
// 4 rowgrps x 2 colgrps; thread owns 4 rows x 2 cols. K=256.
// Wp (128KB) loaded via cp.async in 2 halves (2nd overlaps 1st's compute).
// smem floats: As[16][256]=4096 | Ws[256][128]=32768 | lnS/Q 64
#define POOL_SMEM ((4096 + 32768 + 64) * 4)
__global__ void __launch_bounds__(256, 1)
pool_gemm_ln_kernel(const float* __restrict__ Wp, const float* __restrict__ bp,
                    const float* __restrict__ gp, const float* __restrict__ bgp) {
    extern __shared__ float smem[];
    float (*As)[256] = reinterpret_cast<float (*)[256]>(smem);
    float (*Ws)[DD]  = reinterpret_cast<float (*)[DD]>(smem + 4096);
    float (*lnS)[16] = reinterpret_cast<float (*)[16]>(smem + 4096 + 32768);
    float (*lnQ)[16] = reinterpret_cast<float (*)[16]>(smem + 4096 + 32768 + 32);

    const int tid = threadIdx.x;
    const int lane = tid & 31, wid = tid >> 5;
    const int rg = wid & 3, cg = wid >> 2;
    const int rg4 = rg * 4;
    const int c2 = cg * 64 + lane * 2;
    const int row0 = blockIdx.x * 16;
    const int b = row0 >> 8;
    const int nbase = row0 & 255;

    // issue Wp loads: 2 halves of 128 k-rows, 16 cp.async each per thread
    uint32_t ws_base = (uint32_t)__cvta_generic_to_shared(&Ws[0][0]);
#pragma unroll
    for (int h = 0; h < 2; h++) {
#pragma unroll
        for (int i = 0; i < 16; i++) {
            int t16 = tid + i * 256;            // 0..4095
            int k = h * 128 + (t16 >> 5);
            int c4 = (t16 & 31) << 2;
            cp_async16(ws_base + (uint32_t)(k * DD + c4) * 4, Wp + k * DD + c4);
        }
        cp_commit();
    }

    // fill As: h part (cols 0..127) + synthesized pooled part (cols 128..255)
#pragma unroll
    for (int i = 0; i < 2; i++) {
        int idx4 = (tid + i * 256) * 4;
        int r = idx4 >> 7, k = idx4 & 127;
        *reinterpret_cast<float4*>(&As[r][k]) =
            *reinterpret_cast<const float4*>(&g_h[row0 * DD + idx4]);
    }
#pragma unroll
    for (int i = 0; i < 8; i++) {
        int idx = tid + i * 256;                // 0..2047
        int r = idx >> 7, k = idx & 127;
        int am = g_i1[b * DD + k];
        float m1 = g_m1[b * DD + k], m2 = g_m2[b * DD + k];
        As[r][128 + k] = (nbase + r == am) ? m2 : m1;
    }

    float acc[4][2];
#pragma unroll
    for (int r = 0; r < 4; r++) { acc[r][0] = 0.f; acc[r][1] = 0.f; }

    cp_wait1();          // first half of Wp ready
    __syncthreads();     // + As visible

#pragma unroll 4
    for (int k0 = 0; k0 < 128; k0 += 4) {
        float a[4][4];
#pragma unroll
        for (int r = 0; r < 4; r++)
            *reinterpret_cast<float4*>(a[r]) =
                *reinterpret_cast<const float4*>(&As[rg4 + r][k0]);
#pragma unroll
        for (int kk = 0; kk < 4; kk++) {
            float2 w = *reinterpret_cast<const float2*>(&Ws[k0 + kk][c2]);
#pragma unroll
            for (int r = 0; r < 4; r++) {
                acc[r][0] = fmaf(a[r][kk], w.x, acc[r][0]);
                acc[r][1] = fmaf(a[r][kk], w.y, acc[r][1]);
            }
        }
    }

    cp_wait0();          // second half ready
    __syncthreads();

#pragma unroll 4
    for (int k0 = 128; k0 < 256; k0 += 4) {
        float a[4][4];
#pragma unroll
        for (int r = 0; r < 4; r++)
            *reinterpret_cast<float4*>(a[r]) =
                *reinterpret_cast<const float4*>(&As[rg4 + r][k0]);
#pragma unroll
        for (int kk = 0; kk < 4; kk++) {
            float2 w = *reinterpret_cast<const float2*>(&Ws[k0 + kk][c2]);
#pragma unroll
            for (int r = 0; r < 4; r++) {
                acc[r][0] = fmaf(a[r][kk], w.x, acc[r][0]);
                acc[r][1] = fmaf(a[r][kk], w.y, acc[r][1]);
            }
        }
    }

    // epilogue: +bias +residual (As h-part), LN (warp partial + 2-way combine)
    float v[4][2], s[4], q[4];
    float bp0 = bp[c2], bp1 = bp[c2 + 1];
#pragma unroll
    for (int r = 0; r < 4; r++) {
        v[r][0] = acc[r][0] + bp0 + As[rg4 + r][c2];
        v[r][1] = acc[r][1] + bp1 + As[rg4 + r][c2 + 1];
        s[r] = v[r][0] + v[r][1];
        q[r] = v[r][0] * v[r][0] + v[r][1] * v[r][1];
    }
#pragma unroll
    for (int o = 16; o > 0; o >>= 1)
#pragma unroll
        for (int r = 0; r < 4; r++) {
            s[r] += __shfl_xor_sync(0xffffffffu, s[r], o);
            q[r] += __shfl_xor_sync(0xffffffffu, q[r], o);
        }
    if (lane == 0)
#pragma unroll
        for (int r = 0; r < 4; r++) { lnS[cg][rg4 + r] = s[r]; lnQ[cg][rg4 + r] = q[r]; }
    __syncthreads();
    float g0 = gp[c2], g1 = gp[c2 + 1], e0 = bgp[c2], e1 = bgp[c2 + 1];
#pragma unroll
    for (int r = 0; r < 4; r++) {
        float S = lnS[0][rg4 + r] + lnS[1][rg4 + r];
        float Q = lnQ[0][rg4 + r] + lnQ[1][rg4 + r];
        float mean = S * (1.0f / DD);
        float rstd = rsqrtf(Q * (1.0f / DD) - mean * mean + LN_EPS);
        float2 o;
        o.x = (v[r][0] - mean) * rstd * g0 + e0;
        o.y = (v[r][1] - mean) * rstd * g1 + e1;
        *reinterpret_cast<float2*>(&g_h[(row0 + rg4 + r) * DD + c2]) = o;
    }
}

// ===================== fused FF =====================
// h' = LN(h + relu(h@W1+b1)@W2 + b2). 4 H-chunks of 128.
// smem floats: hs[16][128]=2048 | W1c[2][128][128]=32768 | W2c[128][128]=16384
//              | Us[16][128]=2048 | lnS/Q 64  -> 213504 B
#define FF_SMEM ((2048 + 32768 + 16384 + 2048 + 64) * 4)
template <bool FINAL>
__global__ void __launch_bounds__(256, 1)
ff_fused_kernel(const float* __restrict__ W1, const float* __restrict__ b1,
                const float* __restrict__ W2, const float* __restrict__ b2,
                const float* __restrict__ gf, const float* __restrict__ bgf,
                float* __restrict__ out) {
    extern __shared__ float smem[];
    float (*hs)[DD]  = reinterpret_cast<float (*)[DD]>(smem);                  // 16x128
    float* W1c       = smem + 2048;                                            // [2][128][128]
    float (*W2c)[DD] = reinterpret_cast<float (*)[DD]>(smem + 2048 + 32768);   // 128x128
    float (*Us)[DD]  = reinterpret_cast<float (*)[DD]>(smem + 2048 + 32768 + 16384);
    float (*lnS)[16] = reinterpret_cast<float (*)[16]>(smem + 2048 + 32768 + 16384 + 2048);
    float (*lnQ)[16] = reinterpret_cast<float (*)[16]>(smem + 2048 + 32768 + 16384 + 2048 + 32);

    const int tid = threadIdx.x;
    const int lane = tid & 31, wid = tid >> 5;
    const int rg = wid & 3, cg = wid >> 2;
    const int rg4 = rg * 4;
    const int c2 = cg * 64 + lane * 2;
    const int row0 = blockIdx.x * 16;

    const uint32_t w1s = (uint32_t)__cvta_generic_to_shared(W1c);
    const uint32_t w2s = (uint32_t)__cvta_generic_to_shared(&W2c[0][0]);

    // issue chunk-0 weight loads immediately
    {
#pragma unroll
        for (int i = 0; i < 16; i++) {           // W1 chunk 0 -> buf 0
            int t16 = tid + i * 256;
            int k = t16 >> 5, c4 = (t16 & 31) << 2;
            cp_async16(w1s + (uint32_t)(k * DD + c4) * 4, W1 + k * HH + c4);
        }
        cp_commit();
#pragma unroll
        for (int i = 0; i < 16; i++) {           // W2 chunk 0
            int t16 = tid + i * 256;
            int k = t16 >> 5, c4 = (t16 & 31) << 2;
            cp_async16(w2s + (uint32_t)(k * DD + c4) * 4, W2 + k * DD + c4);
        }
        cp_commit();
    }

    // load h rows (doubles as residual)
#pragma unroll
    for (int i = 0; i < 2; i++) {
        int idx4 = (tid + i * 256) * 4;
        *reinterpret_cast<float4*>(&hs[idx4 >> 7][idx4 & 127]) =
            *reinterpret_cast<const float4*>(&g_h[row0 * DD + idx4]);
    }

    float acc2[4][2];
#pragma unroll
    for (int r = 0; r < 4; r++) { acc2[r][0] = 0.f; acc2[r][1] = 0.f; }

    for (int ci = 0; ci < 4; ci++) {
        const int c0 = ci * 128;
        const float* W1b = W1c + (ci & 1) * 16384;

        cp_wait1();          // W1(ci) ready (W2(ci) may still fly)
        __syncthreads();     // + hs/Us hazards

        // ---- ff1: acc1 = hs @ W1b ----
        float acc1[4][2];
#pragma unroll
        for (int r = 0; r < 4; r++) { acc1[r][0] = 0.f; acc1[r][1] = 0.f; }
#pragma unroll 4
        for (int k0 = 0; k0 < 128; k0 += 4) {
            float a[4][4];
#pragma unroll
            for (int r = 0; r < 4; r++)
                *reinterpret_cast<float4*>(a[r]) =
                    *reinterpret_cast<const float4*>(&hs[rg4 + r][k0]);
#pragma unroll
            for (int kk = 0; kk < 4; kk++) {
                float2 w = *reinterpret_cast<const float2*>(&W1b[(k0 + kk) * DD + c2]);
#pragma unroll
                for (int r = 0; r < 4; r++) {
                    acc1[r][0] = fmaf(a[r][kk], w.x, acc1[r][0]);
                    acc1[r][1] = fmaf(a[r][kk], w.y, acc1[r][1]);
                }
            }
        }
        // Us = relu(acc1 + b1)
        {
            float bb0 = b1[c0 + c2], bb1 = b1[c0 + c2 + 1];
#pragma unroll
            for (int r = 0; r < 4; r++) {
                float2 u;
                u.x = fmaxf(acc1[r][0] + bb0, 0.0f);
                u.y = fmaxf(acc1[r][1] + bb1, 0.0f);
                *reinterpret_cast<float2*>(&Us[rg4 + r][c2]) = u;
            }
        }

        // prefetch W1(ci+1) into the other buffer (overlaps ff2)
        if (ci < 3) {
            uint32_t dst = w1s + (uint32_t)(((ci + 1) & 1) * 16384) * 4;
            const float* src = W1 + c0 + 128;
#pragma unroll
            for (int i = 0; i < 16; i++) {
                int t16 = tid + i * 256;
                int k = t16 >> 5, c4 = (t16 & 31) << 2;
                cp_async16(dst + (uint32_t)(k * DD + c4) * 4, src + k * HH + c4);
            }
            cp_commit();
        }

        if (ci < 3) cp_wait1(); else cp_wait0();   // W2(ci) ready
        __syncthreads();                            // + Us visible

        // ---- ff2 partial: acc2 += Us @ W2c ----
#pragma unroll 4
        for (int k0 = 0; k0 < 128; k0 += 4) {
            float a[4][4];
#pragma unroll
            for (int r = 0; r < 4; r++)
                *reinterpret_cast<float4*>(a[r]) =
                    *reinterpret_cast<const float4*>(&Us[rg4 + r][k0]);
#pragma unroll
            for (int kk = 0; kk < 4; kk++) {
                float2 w = *reinterpret_cast<const float2*>(&W2c[k0 + kk][c2]);
#pragma unroll
                for (int r = 0; r < 4; r++) {
                    acc2[r][0] = fmaf(a[r][kk], w.x, acc2[r][0]);
                    acc2[r][1] = fmaf(a[r][kk], w.y, acc2[r][1]);
                }
            }
        }
        __syncthreads();    // W2c fully consumed

        // prefetch W2(ci+1) (overlaps next ff1)
        if (ci < 3) {
            const float* src = W2 + (c0 + 128) * DD;
#pragma unroll
            for (int i = 0; i < 16; i++) {
                int t16 = tid + i * 256;
                int k = t16 >> 5, c4 = (t16 & 31) << 2;
                cp_async16(w2s + (uint32_t)(k * DD + c4) * 4, src + k * DD + c4);
            }
            cp_commit();
        }
    }

    // epilogue: +b2 +residual (hs), LN (warp partial + 2-way combine)
    float v[4][2], s[4], q[4];
    float b20 = b2[c2], b21 = b2[c2 + 1];
#pragma unroll
    for (int r = 0; r < 4; r++) {
        v[r][0] = acc2[r][0] + b20 + hs[rg4 + r][c2];
        v[r][1] = acc2[r][1] + b21 + hs[rg4 + r][c2 + 1];
        s[r] = v[r][0] + v[r][1];
        q[r] = v[r][0] * v[r][0] + v[r][1] * v[r][1];
    }
#pragma unroll
    for (int o = 16; o > 0; o >>= 1)
#pragma unroll
        for (int r = 0; r < 4; r++) {
            s[r] += __shfl_xor_sync(0xffffffffu, s[r], o);
            q[r] += __shfl_xor_sync(0xffffffffu, q[r], o);
        }
    if (lane == 0)
#pragma unroll
        for (int r = 0; r < 4; r++) { lnS[cg][rg4 + r] = s[r]; lnQ[cg][rg4 + r] = q[r]; }
    __syncthreads();
    float g0 = gf[c2], g1 = gf[c2 + 1], e0 = bgf[c2], e1 = bgf[c2 + 1];
#pragma unroll
    for (int r = 0; r < 4; r++) {
        float S = lnS[0][rg4 + r] + lnS[1][rg4 + r];
        float Q = lnQ[0][rg4 + r] + lnQ[1][rg4 + r];
        float mean = S * (1.0f / DD);
        float rstd = rsqrtf(Q * (1.0f / DD) - mean * mean + LN_EPS);
        float2 o;
        o.x = (v[r][0] - mean) * rstd * g0 + e0;
        o.y = (v[r][1] - mean) * rstd * g1 + e1;
        int row = row0 + rg4 + r;
        if (FINAL) *reinterpret_cast<float2*>(&out[row * DD + c2]) = o;
        else       *reinterpret_cast<float2*>(&g_h[row * DD + c2]) = o;
    }
}

extern "C" void kernel_launch(void* const* d_in, const int* in_sizes, int n_in,
                              void* d_out, int out_size) {
    const float* x   = (const float*)d_in[0];   // (8,256,2)
    const float* We  = (const float*)d_in[1];   // (2,128)
    const float* be  = (const float*)d_in[2];
    const float* ge  = (const float*)d_in[3];
    const float* bge = (const float*)d_in[4];
    const float* Wp  = (const float*)d_in[5];   // (2,256,128)
    const float* bp  = (const float*)d_in[6];
    const float* gp  = (const float*)d_in[7];
    const float* bgp = (const float*)d_in[8];
    const float* W1  = (const float*)d_in[9];   // (2,128,512)
    const float* b1  = (const float*)d_in[10];
    const float* W2  = (const float*)d_in[11];  // (2,512,128)
    const float* b2  = (const float*)d_in[12];
    const float* gf  = (const float*)d_in[13];
    const float* bgf = (const float*)d_in[14];
    float* out = (float*)d_out;                 // (8,256,128) fp32

    cudaFuncSetAttribute(pool_gemm_ln_kernel,
                         cudaFuncAttributeMaxDynamicSharedMemorySize, POOL_SMEM);
    cudaFuncSetAttribute(ff_fused_kernel<false>,
                         cudaFuncAttributeMaxDynamicSharedMemorySize, FF_SMEM);
    cudaFuncSetAttribute(ff_fused_kernel<true>,
                         cudaFuncAttributeMaxDynamicSharedMemorySize, FF_SMEM);

    embed_ln_kernel<<<T_TOK, 128>>>(x, We, be, ge, bge);

    for (int i = 0; i < 2; i++) {
        stats_kernel<<<NB, dim3(128, 4)>>>();

        pool_gemm_ln_kernel<<<T_TOK / 16, 256, POOL_SMEM>>>(
            Wp + i * 2 * DD * DD, bp + i * DD, gp + i * DD, bgp + i * DD);

        if (i == 1)
            ff_fused_kernel<true><<<T_TOK / 16, 256, FF_SMEM>>>(
                W1 + i * DD * HH, b1 + i * HH, W2 + i * HH * DD, b2 + i * DD,
                gf + i * DD, bgf + i * DD, out);
        else
            ff_fused_kernel<false><<<T_TOK / 16, 256, FF_SMEM>>>(
                W1 + i * DD * HH, b1 + i * HH, W2 + i * HH * DD, b2 + i * DD,
                gf + i * DD, bgf + i * DD, nullptr);
    }
}